// round 6
// baseline (speedup 1.0000x reference)
#include <cuda_runtime.h>
#include <cuda_bf16.h>
#include <cstdint>
#include <cstddef>

// ============================================================================
// RNN_4715874091371 — GB300 sm_103a (compute_103 PTX)
//   Z = X @ W_ih^T + (b_ih+b_hh)   bf16 m16n8k16 GEMM (65536x1024x1024)
//   h_t = tanh(Z_t + h_{t-1} @ W_hh^T)  persistent tf32 kernel, 256 CTAs,
//                                       sw grid barrier, 63 steps
//   p = sigmoid(h @ W_out^T + b_out);  loss = BCE(p, y >= 1e-5)
// ============================================================================

static constexpr int TT = 64;
static constexpr int BB = 1024;
static constexpr int HH = 1024;
static constexpr int NSTEP_CTAS = 256;            // 32 m-tiles x 8 n-tiles

// ---------------- device scratch (allocation-free rule) --------------------
__device__ __nv_bfloat16 g_Xbf[(size_t)BB * TT * HH];    // av in bf16 (128MB)
__device__ __nv_bfloat16 g_Wihbf[(size_t)HH * HH];       // W_ih bf16
__device__ float g_Whh[(size_t)HH * HH];                  // W_hh tf32-rounded
__device__ float g_Z[(size_t)TT * BB * HH];               // [t][b][h]
__device__ float g_h[2][(size_t)BB * HH];
__device__ float g_p[BB];
__device__ unsigned g_bar;

#define DEVI __device__ __forceinline__

DEVI uint32_t smem_u32(const void* p) {
    uint32_t a;
    asm("{ .reg .u64 t; cvta.to.shared.u64 t, %1; cvt.u32.u64 %0, t; }"
        : "=r"(a) : "l"(p));
    return a;
}
DEVI float tf32_rn(float x) {
    uint32_t u;
    asm("cvt.rna.tf32.f32 %0, %1;" : "=r"(u) : "f"(x));
    return __uint_as_float(u);
}

#define CPA16(dst_b, src) \
    asm volatile("cp.async.cg.shared.global [%0], [%1], 16;" :: "r"(dst_b), "l"(src))
#define CPC()    asm volatile("cp.async.commit_group;" ::: "memory")
#define CPW2()   asm volatile("cp.async.wait_group 2;" ::: "memory")

// tf32 m16n8k8:  D += A*B
#define MMA_TF32(d, a, b)                                                       \
    asm("mma.sync.aligned.m16n8k8.row.col.f32.tf32.tf32.f32 "                   \
        "{%0,%1,%2,%3}, {%4,%5,%6,%7}, {%8,%9}, {%0,%1,%2,%3};"                 \
        : "+f"((d)[0]), "+f"((d)[1]), "+f"((d)[2]), "+f"((d)[3])                \
        : "r"((a)[0]), "r"((a)[1]), "r"((a)[2]), "r"((a)[3]),                   \
          "r"((b)[0]), "r"((b)[1]))

// bf16 m16n8k16: D += A*B
#define MMA_BF16(d, a, b)                                                       \
    asm("mma.sync.aligned.m16n8k16.row.col.f32.bf16.bf16.f32 "                  \
        "{%0,%1,%2,%3}, {%4,%5,%6,%7}, {%8,%9}, {%0,%1,%2,%3};"                 \
        : "+f"((d)[0]), "+f"((d)[1]), "+f"((d)[2]), "+f"((d)[3])                \
        : "r"((a)[0]), "r"((a)[1]), "r"((a)[2]), "r"((a)[3]),                   \
          "r"((b)[0]), "r"((b)[1]))

// ============================================================================
// Big GEMM (bf16): Z = Xbf @ Wihbf^T + (b_ih+b_hh). Tile 128x128, K-chunk 64
// halves (32 words/row, pad to 36), 16 chunks, 3 stages, 2 CTAs/SM.
// grid(x = 8 n-tiles [fast], y = 512 m-tiles).
// ============================================================================
__global__ __launch_bounds__(256, 2)
void gemm_big(const float* __restrict__ bih, const float* __restrict__ bhh)
{
    constexpr int SASZ = 128 * 36, SBSZ = 128 * 36, STG = SASZ + SBSZ; // words
    extern __shared__ __align__(16) uint32_t sm[];
    const uint32_t smb = smem_u32(sm);

    const int tid  = threadIdx.x;
    const int lane = tid & 31;
    const int wid  = tid >> 5;
    const int wm   = wid >> 2;             // 2 x 4 warp grid; warp tile 64x32
    const int wn   = wid & 3;
    const int n0   = blockIdx.x * 128;
    const int m0   = blockIdx.y * 128;

    auto load_stage = [&](int c, int s) {
        const int kf = c * 64;                               // in halves
        const uint32_t ab = smb + (uint32_t)(s * STG) * 4;
        const uint32_t bb = ab + (uint32_t)SASZ * 4;
        #pragma unroll
        for (int i = 0; i < 4; ++i) {                        // A: 128 x 128B
            int e = tid + i * 256, r = e >> 3, j = e & 7;
            CPA16(ab + (uint32_t)(r * 36 + j * 4) * 4,
                  g_Xbf + (size_t)(m0 + r) * HH + kf + j * 8);
        }
        #pragma unroll
        for (int i = 0; i < 4; ++i) {                        // B: 128 x 128B
            int e = tid + i * 256, r = e >> 3, j = e & 7;
            CPA16(bb + (uint32_t)(r * 36 + j * 4) * 4,
                  g_Wihbf + (size_t)(n0 + r) * HH + kf + j * 8);
        }
    };

    #pragma unroll
    for (int c = 0; c < 3; ++c) { load_stage(c, c); CPC(); }

    float acc[4][4][4];
    #pragma unroll
    for (int mi = 0; mi < 4; ++mi)
        #pragma unroll
        for (int nf = 0; nf < 4; ++nf)
            #pragma unroll
            for (int j = 0; j < 4; ++j) acc[mi][nf][j] = 0.f;

    const int arow  = wm * 64 + (lane >> 2);
    const int q     = lane & 3;

    for (int c = 0; c < 16; ++c) {
        CPW2();
        __syncthreads();
        const uint32_t* sA = sm + (c % 3) * STG;
        const uint32_t* sB = sA + SASZ;
        #pragma unroll
        for (int ks = 0; ks < 4; ++ks) {                     // k16 per MMA
            const int col = ks * 8 + q;                      // word index
            uint32_t a[4][4];
            #pragma unroll
            for (int mi = 0; mi < 4; ++mi) {
                const uint32_t* p = sA + (arow + mi * 16) * 36 + col;
                a[mi][0] = p[0];
                a[mi][1] = p[8 * 36];
                a[mi][2] = p[4];
                a[mi][3] = p[8 * 36 + 4];
            }
            uint32_t b[4][2];
            #pragma unroll
            for (int nf = 0; nf < 4; ++nf) {
                const uint32_t* p = sB + (wn * 32 + nf * 8 + (lane >> 2)) * 36 + col;
                b[nf][0] = p[0];
                b[nf][1] = p[4];
            }
            #pragma unroll
            for (int mi = 0; mi < 4; ++mi)
                #pragma unroll
                for (int nf = 0; nf < 4; ++nf)
                    MMA_BF16(acc[mi][nf], a[mi], b[nf]);
        }
        __syncthreads();
        if (c + 3 < 16) load_stage(c + 3, c % 3);
        CPC();
    }

    // epilogue: + biases, scatter to g_Z[t][b][n]  (m = b*64 + t)
    #pragma unroll
    for (int mi = 0; mi < 4; ++mi) {
        const int r0 = m0 + wm * 64 + mi * 16 + (lane >> 2);
        #pragma unroll
        for (int nf = 0; nf < 4; ++nf) {
            const int cg = n0 + wn * 32 + nf * 8 + q * 2;
            const float bsum0 = bih[cg] + bhh[cg];
            const float bsum1 = bih[cg + 1] + bhh[cg + 1];
            #pragma unroll
            for (int half = 0; half < 2; ++half) {
                const int r = r0 + half * 8;
                float2 o;
                o.x = acc[mi][nf][half * 2 + 0] + bsum0;
                o.y = acc[mi][nf][half * 2 + 1] + bsum1;
                const int b = r >> 6, t = r & 63;
                *(float2*)(g_Z + ((size_t)t * BB + b) * HH + cg) = o;
            }
        }
    }
}

// ============================================================================
// Persistent steps (tf32): 256 CTAs, tile 32x128, 2 CTAs/SM, grid barrier.
//   t=0: h0 = tanh(Z_0);  t>=1: h_t = tanh(Z_t + h_{t-1} @ W_hh^T)
// ============================================================================
__global__ __launch_bounds__(256, 2)
void steps_k()
{
    constexpr int MT = 32, NT = 128;
    constexpr int SASZ = MT * 36, SBSZ = NT * 36, STG = SASZ + SBSZ;  // words
    extern __shared__ __align__(16) uint32_t sm[];
    float* smf = (float*)sm;
    const uint32_t smb = smem_u32(sm);

    const int tid  = threadIdx.x;
    const int lane = tid & 31;
    const int wid  = tid >> 5;             // 1 x 8 warp grid; warp tile 32x16
    const int m0   = (blockIdx.x >> 3) * MT;
    const int n0   = (blockIdx.x & 7) * NT;

    // ---- t = 0 ----
    for (int e = tid; e < MT * NT; e += 256) {
        int r = e >> 7, c = e & 127;
        size_t idx = (size_t)(m0 + r) * HH + n0 + c;
        g_h[0][idx] = tf32_rn(tanhf(g_Z[idx]));
    }
    __syncthreads();
    if (tid == 0) { __threadfence(); atomicAdd(&g_bar, 1); }

    const int arow = lane >> 2;
    const int q    = lane & 3;

    for (int t = 1; t < TT; ++t) {
        const float* __restrict__ Asrc = g_h[(t - 1) & 1];
        float*       __restrict__ out  = g_h[t & 1];
        const float* __restrict__ Zt   = g_Z + (size_t)t * BB * HH;

        // Z prefetch (independent of h): hide behind barrier wait
        float2 zf[2][2][2];
        #pragma unroll
        for (int mi = 0; mi < 2; ++mi)
            #pragma unroll
            for (int nf = 0; nf < 2; ++nf) {
                const int cg = n0 + wid * 16 + nf * 8 + q * 2;
                #pragma unroll
                for (int half = 0; half < 2; ++half) {
                    const int r = m0 + mi * 16 + arow + half * 8;
                    zf[mi][nf][half] = *(const float2*)(Zt + (size_t)r * HH + cg);
                }
            }

        if (tid == 0) {
            const unsigned tgt = (unsigned)NSTEP_CTAS * (unsigned)t;
            while (*(volatile unsigned*)&g_bar < tgt) __nanosleep(32);
            __threadfence();
        }
        __syncthreads();

        auto load_stage = [&](int c, int s) {
            const int kf = c * 32;
            const uint32_t ab = smb + (uint32_t)(s * STG) * 4;
            const uint32_t bb = ab + (uint32_t)SASZ * 4;
            {                                                // A: 32 x 128B
                int r = tid >> 3, j = tid & 7;
                if (r < MT)
                    CPA16(ab + (uint32_t)(r * 36 + j * 4) * 4,
                          Asrc + (size_t)(m0 + r) * HH + kf + j * 4);
            }
            #pragma unroll
            for (int i = 0; i < 4; ++i) {                    // B: 128 x 128B
                int e = tid + i * 256, r = e >> 3, j = e & 7;
                CPA16(bb + (uint32_t)(r * 36 + j * 4) * 4,
                      g_Whh + (size_t)(n0 + r) * HH + kf + j * 4);
            }
        };

        #pragma unroll
        for (int c = 0; c < 3; ++c) { load_stage(c, c); CPC(); }

        float acc[2][2][4];
        #pragma unroll
        for (int mi = 0; mi < 2; ++mi)
            #pragma unroll
            for (int nf = 0; nf < 2; ++nf)
                #pragma unroll
                for (int j = 0; j < 4; ++j) acc[mi][nf][j] = 0.f;

        for (int c = 0; c < 32; ++c) {
            CPW2();
            __syncthreads();
            if (c + 3 < 32) load_stage(c + 3, (c + 3) & 3);
            CPC();
            const float* sA = smf + (c & 3) * STG;
            const float* sB = sA + SASZ;
            #pragma unroll
            for (int ks = 0; ks < 4; ++ks) {
                const int col = ks * 8 + q;
                uint32_t a[2][4];
                #pragma unroll
                for (int mi = 0; mi < 2; ++mi) {
                    const float* p = sA + (arow + mi * 16) * 36 + col;
                    a[mi][0] = __float_as_uint(p[0]);
                    a[mi][1] = __float_as_uint(p[8 * 36]);
                    a[mi][2] = __float_as_uint(p[4]);
                    a[mi][3] = __float_as_uint(p[8 * 36 + 4]);
                }
                uint32_t b[2][2];
                #pragma unroll
                for (int nf = 0; nf < 2; ++nf) {
                    const float* p = sB + (wid * 16 + nf * 8 + arow) * 36 + col;
                    b[nf][0] = __float_as_uint(p[0]);
                    b[nf][1] = __float_as_uint(p[4]);
                }
                #pragma unroll
                for (int mi = 0; mi < 2; ++mi)
                    #pragma unroll
                    for (int nf = 0; nf < 2; ++nf)
                        MMA_TF32(acc[mi][nf], a[mi], b[nf]);
            }
            __syncthreads();
        }

        // epilogue: tanh(acc + Z_t) -> h[t&1]
        #pragma unroll
        for (int mi = 0; mi < 2; ++mi)
            #pragma unroll
            for (int nf = 0; nf < 2; ++nf) {
                const int cg = n0 + wid * 16 + nf * 8 + q * 2;
                #pragma unroll
                for (int half = 0; half < 2; ++half) {
                    const int r = m0 + mi * 16 + arow + half * 8;
                    float2 o;
                    o.x = tf32_rn(tanhf(acc[mi][nf][half * 2 + 0] + zf[mi][nf][half].x));
                    o.y = tf32_rn(tanhf(acc[mi][nf][half * 2 + 1] + zf[mi][nf][half].y));
                    *(float2*)(out + (size_t)r * HH + cg) = o;
                }
            }
        __syncthreads();
        if (tid == 0) { __threadfence(); atomicAdd(&g_bar, 1); }
    }
}

// ----------------------------- small kernels --------------------------------
__global__ void conv_av_k(const float4* __restrict__ av, int n8) {
    int i = blockIdx.x * blockDim.x + threadIdx.x;       // 8 floats per thread
    if (i < n8) {
        float4 a = av[2 * i], b = av[2 * i + 1];
        __nv_bfloat162 p0 = __floats2bfloat162_rn(a.x, a.y);
        __nv_bfloat162 p1 = __floats2bfloat162_rn(a.z, a.w);
        __nv_bfloat162 p2 = __floats2bfloat162_rn(b.x, b.y);
        __nv_bfloat162 p3 = __floats2bfloat162_rn(b.z, b.w);
        uint4 o = make_uint4(*(uint32_t*)&p0, *(uint32_t*)&p1,
                             *(uint32_t*)&p2, *(uint32_t*)&p3);
        ((uint4*)g_Xbf)[i] = o;
    }
}

__global__ void conv_W_k(const float4* __restrict__ wih,
                         const float4* __restrict__ whh, int n4) {
    int i = blockIdx.x * blockDim.x + threadIdx.x;
    if (i == 0) g_bar = 0;                                // reset grid barrier
    if (i < n4) {
        float4 a = wih[i];
        __nv_bfloat162 p0 = __floats2bfloat162_rn(a.x, a.y);
        __nv_bfloat162 p1 = __floats2bfloat162_rn(a.z, a.w);
        ((uint2*)g_Wihbf)[i] = make_uint2(*(uint32_t*)&p0, *(uint32_t*)&p1);
        float4 b = whh[i];
        b.x = tf32_rn(b.x); b.y = tf32_rn(b.y); b.z = tf32_rn(b.z); b.w = tf32_rn(b.w);
        ((float4*)g_Whh)[i] = b;
    }
}

__global__ void head_k(const float* __restrict__ Wout,
                       const float* __restrict__ bout) {
    int wid = threadIdx.x >> 5, lane = threadIdx.x & 31;
    int row = blockIdx.x * 8 + wid;
    const float4* hr = (const float4*)(g_h[1] + (size_t)row * HH);
    const float4* wr = (const float4*)Wout;
    float s = 0.f;
    for (int i = lane; i < HH / 4; i += 32) {
        float4 a = hr[i], b = wr[i];
        s += a.x * b.x + a.y * b.y + a.z * b.z + a.w * b.w;
    }
    #pragma unroll
    for (int o = 16; o; o >>= 1) s += __shfl_xor_sync(0xFFFFFFFFu, s, o);
    if (lane == 0) g_p[row] = 1.f / (1.f + expf(-(s + bout[0])));
}

__global__ void loss_k(const float* __restrict__ y, float* __restrict__ out,
                       int out_size) {
    __shared__ float red[32];
    int tid = threadIdx.x;                                // 1024 threads
    float pv = g_p[tid];
    float yb = (y[tid] >= 1e-5f) ? 1.f : 0.f;
    float term = yb * fmaxf(logf(pv), -100.f)
               + (1.f - yb) * fmaxf(log1pf(-pv), -100.f);
    #pragma unroll
    for (int o = 16; o; o >>= 1) term += __shfl_xor_sync(0xFFFFFFFFu, term, o);
    if ((tid & 31) == 0) red[tid >> 5] = term;
    __syncthreads();
    if (tid < 32) {
        float v = red[tid];
        #pragma unroll
        for (int o = 16; o; o >>= 1) v += __shfl_xor_sync(0xFFFFFFFFu, v, o);
        if (tid == 0 && out_size != BB) out[0] = -v / (float)BB;
    }
    if (out_size >= 1 + BB)      out[1 + tid] = pv;
    else if (out_size == BB)     out[tid] = pv;
    for (int i = 1 + BB + tid; i < out_size; i += BB) out[i] = 0.f;
}

// ------------------------------- launcher -----------------------------------
extern "C" void kernel_launch(void* const* d_in, const int* in_sizes, int n_in,
                              void* d_out, int out_size) {
    const float* av   = (const float*)d_in[3];
    const float* y    = (const float*)d_in[4];
    const float* Wih  = (const float*)d_in[5];
    const float* bih  = (const float*)d_in[6];
    const float* Whh  = (const float*)d_in[7];
    const float* bhh  = (const float*)d_in[8];
    const float* Wout = (const float*)d_in[9];
    const float* bout = (const float*)d_in[10];
    (void)in_sizes; (void)n_in;

    constexpr int SMEM_BIG  = 3 * (128 * 36 + 128 * 36) * 4;   // 110592 B
    constexpr int SMEM_STEP = 4 * (32 * 36 + 128 * 36) * 4;    //  92160 B
    cudaFuncSetAttribute(gemm_big,
                         cudaFuncAttributeMaxDynamicSharedMemorySize, SMEM_BIG);
    cudaFuncSetAttribute(steps_k,
                         cudaFuncAttributeMaxDynamicSharedMemorySize, SMEM_STEP);

    // 1) conversions (av -> bf16; W_ih -> bf16; W_hh -> tf32) + barrier reset
    conv_av_k<<<(BB * TT * HH / 8 + 255) / 256, 256>>>((const float4*)av,
                                                       BB * TT * HH / 8);
    conv_W_k<<<(HH * HH / 4 + 255) / 256, 256>>>(
        (const float4*)Wih, (const float4*)Whh, HH * HH / 4);

    // 2) Z = X @ W_ih^T + b_ih + b_hh   (bf16 tensor cores)
    gemm_big<<<dim3(8, 512), 256, SMEM_BIG>>>(bih, bhh);

    // 3) persistent recurrence (tf32), includes h0 = tanh(Z_0)
    steps_k<<<NSTEP_CTAS, 256, SMEM_STEP>>>();

    // 4) head + loss (final h in g_h[1])
    head_k<<<128, 256>>>(Wout, bout);
    loss_k<<<1, BB>>>(y, (float*)d_out, out_size);
}

// round 7
// speedup vs baseline: 1.2406x; 1.2406x over previous
#include <cuda_runtime.h>
#include <cuda_bf16.h>
#include <cstdint>
#include <cstddef>

// ============================================================================
// RNN_4715874091371 — GB300 sm_103a (compute_103 PTX)
//   Z = X @ W_ih^T + (b_ih+b_hh)   bf16 m16n8k16 GEMM (65536x1024x1024)
//   h_t = tanh(Z_t + h_{t-1} @ W_hh^T)  persistent tf32 kernel, 128 CTAs,
//       CTA tile 64x128, warp tile 32x32, K-chunk 64, single-sync pipeline
//   p = sigmoid(h @ W_out^T + b_out);  loss = BCE(p, y >= 1e-5)
// ============================================================================

static constexpr int TT = 64;
static constexpr int BB = 1024;
static constexpr int HH = 1024;
static constexpr int NSTEP_CTAS = 128;            // 16 m-tiles x 8 n-tiles

// ---------------- device scratch (allocation-free rule) --------------------
__device__ __nv_bfloat16 g_Xbf[(size_t)BB * TT * HH];    // av in bf16 (128MB)
__device__ __nv_bfloat16 g_Wihbf[(size_t)HH * HH];       // W_ih bf16
__device__ float g_Whh[(size_t)HH * HH];                  // W_hh tf32-rounded
__device__ float g_Z[(size_t)TT * BB * HH];               // [t][b][h]
__device__ float g_h[2][(size_t)BB * HH];
__device__ float g_p[BB];
__device__ unsigned g_bar;

#define DEVI __device__ __forceinline__

DEVI uint32_t smem_u32(const void* p) {
    uint32_t a;
    asm("{ .reg .u64 t; cvta.to.shared.u64 t, %1; cvt.u32.u64 %0, t; }"
        : "=r"(a) : "l"(p));
    return a;
}
DEVI float tf32_rn(float x) {
    uint32_t u;
    asm("cvt.rna.tf32.f32 %0, %1;" : "=r"(u) : "f"(x));
    return __uint_as_float(u);
}

#define CPA16(dst_b, src) \
    asm volatile("cp.async.cg.shared.global [%0], [%1], 16;" :: "r"(dst_b), "l"(src))
#define CPC()    asm volatile("cp.async.commit_group;" ::: "memory")
#define CPW2()   asm volatile("cp.async.wait_group 2;" ::: "memory")

// tf32 m16n8k8:  D += A*B
#define MMA_TF32(d, a, b)                                                       \
    asm("mma.sync.aligned.m16n8k8.row.col.f32.tf32.tf32.f32 "                   \
        "{%0,%1,%2,%3}, {%4,%5,%6,%7}, {%8,%9}, {%0,%1,%2,%3};"                 \
        : "+f"((d)[0]), "+f"((d)[1]), "+f"((d)[2]), "+f"((d)[3])                \
        : "r"((a)[0]), "r"((a)[1]), "r"((a)[2]), "r"((a)[3]),                   \
          "r"((b)[0]), "r"((b)[1]))

// bf16 m16n8k16: D += A*B
#define MMA_BF16(d, a, b)                                                       \
    asm("mma.sync.aligned.m16n8k16.row.col.f32.bf16.bf16.f32 "                  \
        "{%0,%1,%2,%3}, {%4,%5,%6,%7}, {%8,%9}, {%0,%1,%2,%3};"                 \
        : "+f"((d)[0]), "+f"((d)[1]), "+f"((d)[2]), "+f"((d)[3])                \
        : "r"((a)[0]), "r"((a)[1]), "r"((a)[2]), "r"((a)[3]),                   \
          "r"((b)[0]), "r"((b)[1]))

// ============================================================================
// Big GEMM (bf16): Z = Xbf @ Wihbf^T + (b_ih+b_hh). Tile 128x128, K-chunk 64
// halves (32 words/row, pad to 36), 16 chunks, 3 stages, 2 CTAs/SM.
// ============================================================================
__global__ __launch_bounds__(256, 2)
void gemm_big(const float* __restrict__ bih, const float* __restrict__ bhh)
{
    constexpr int SASZ = 128 * 36, SBSZ = 128 * 36, STG = SASZ + SBSZ; // words
    extern __shared__ __align__(16) uint32_t sm[];
    const uint32_t smb = smem_u32(sm);

    const int tid  = threadIdx.x;
    const int lane = tid & 31;
    const int wid  = tid >> 5;
    const int wm   = wid >> 2;             // 2 x 4 warp grid; warp tile 64x32
    const int wn   = wid & 3;
    const int n0   = blockIdx.x * 128;
    const int m0   = blockIdx.y * 128;

    auto load_stage = [&](int c, int s) {
        const int kf = c * 64;                               // in halves
        const uint32_t ab = smb + (uint32_t)(s * STG) * 4;
        const uint32_t bb = ab + (uint32_t)SASZ * 4;
        #pragma unroll
        for (int i = 0; i < 4; ++i) {                        // A: 128 x 128B
            int e = tid + i * 256, r = e >> 3, j = e & 7;
            CPA16(ab + (uint32_t)(r * 36 + j * 4) * 4,
                  g_Xbf + (size_t)(m0 + r) * HH + kf + j * 8);
        }
        #pragma unroll
        for (int i = 0; i < 4; ++i) {                        // B: 128 x 128B
            int e = tid + i * 256, r = e >> 3, j = e & 7;
            CPA16(bb + (uint32_t)(r * 36 + j * 4) * 4,
                  g_Wihbf + (size_t)(n0 + r) * HH + kf + j * 8);
        }
    };

    #pragma unroll
    for (int c = 0; c < 3; ++c) { load_stage(c, c); CPC(); }

    float acc[4][4][4];
    #pragma unroll
    for (int mi = 0; mi < 4; ++mi)
        #pragma unroll
        for (int nf = 0; nf < 4; ++nf)
            #pragma unroll
            for (int j = 0; j < 4; ++j) acc[mi][nf][j] = 0.f;

    const int arow  = wm * 64 + (lane >> 2);
    const int q     = lane & 3;

    for (int c = 0; c < 16; ++c) {
        CPW2();
        __syncthreads();
        const uint32_t* sA = sm + (c % 3) * STG;
        const uint32_t* sB = sA + SASZ;
        #pragma unroll
        for (int ks = 0; ks < 4; ++ks) {                     // k16 per MMA
            const int col = ks * 8 + q;                      // word index
            uint32_t a[4][4];
            #pragma unroll
            for (int mi = 0; mi < 4; ++mi) {
                const uint32_t* p = sA + (arow + mi * 16) * 36 + col;
                a[mi][0] = p[0];
                a[mi][1] = p[8 * 36];
                a[mi][2] = p[4];
                a[mi][3] = p[8 * 36 + 4];
            }
            uint32_t b[4][2];
            #pragma unroll
            for (int nf = 0; nf < 4; ++nf) {
                const uint32_t* p = sB + (wn * 32 + nf * 8 + (lane >> 2)) * 36 + col;
                b[nf][0] = p[0];
                b[nf][1] = p[4];
            }
            #pragma unroll
            for (int mi = 0; mi < 4; ++mi)
                #pragma unroll
                for (int nf = 0; nf < 4; ++nf)
                    MMA_BF16(acc[mi][nf], a[mi], b[nf]);
        }
        __syncthreads();
        if (c + 3 < 16) load_stage(c + 3, c % 3);
        CPC();
    }

    // epilogue: + biases, scatter to g_Z[t][b][n]  (m = b*64 + t)
    #pragma unroll
    for (int mi = 0; mi < 4; ++mi) {
        const int r0 = m0 + wm * 64 + mi * 16 + (lane >> 2);
        #pragma unroll
        for (int nf = 0; nf < 4; ++nf) {
            const int cg = n0 + wn * 32 + nf * 8 + q * 2;
            const float bsum0 = bih[cg] + bhh[cg];
            const float bsum1 = bih[cg + 1] + bhh[cg + 1];
            #pragma unroll
            for (int half = 0; half < 2; ++half) {
                const int r = r0 + half * 8;
                float2 o;
                o.x = acc[mi][nf][half * 2 + 0] + bsum0;
                o.y = acc[mi][nf][half * 2 + 1] + bsum1;
                const int b = r >> 6, t = r & 63;
                *(float2*)(g_Z + ((size_t)t * BB + b) * HH + cg) = o;
            }
        }
    }
}

// ============================================================================
// Persistent steps (tf32): 128 CTAs, CTA tile 64x128, warp grid 2x4 (warp
// tile 32x32 -> 256B/MMA crossbar), K-chunk 64 (16 chunks), 4 stages,
// SINGLE __syncthreads per chunk, grid barrier between steps.
// ============================================================================
__global__ __launch_bounds__(256, 1)
void steps_k()
{
    constexpr int MT = 64, NT = 128;
    constexpr int RS = 68;                               // row stride (words)
    constexpr int SASZ = MT * RS, SBSZ = NT * RS, STG = SASZ + SBSZ;  // words
    extern __shared__ __align__(16) uint32_t sm[];
    float* smf = (float*)sm;
    const uint32_t smb = smem_u32(sm);

    const int tid  = threadIdx.x;
    const int lane = tid & 31;
    const int wid  = tid >> 5;
    const int wm   = wid >> 2;             // 2 x 4 warp grid; warp tile 32x32
    const int wn   = wid & 3;
    const int m0   = (blockIdx.x >> 3) * MT;
    const int n0   = (blockIdx.x & 7) * NT;

    // ---- t = 0: h0 = tanh(Z_0) ----
    for (int e = tid; e < MT * NT; e += 256) {
        int r = e >> 7, c = e & 127;
        size_t idx = (size_t)(m0 + r) * HH + n0 + c;
        g_h[0][idx] = tf32_rn(tanhf(g_Z[idx]));
    }
    __syncthreads();
    if (tid == 0) { __threadfence(); atomicAdd(&g_bar, 1); }

    const int arow = lane >> 2;
    const int q    = lane & 3;

    for (int t = 1; t < TT; ++t) {
        const float* __restrict__ Asrc = g_h[(t - 1) & 1];
        float*       __restrict__ out  = g_h[t & 1];
        const float* __restrict__ Zt   = g_Z + (size_t)t * BB * HH;

        // Z prefetch (independent of h): hide behind barrier wait
        float2 zf[2][4][2];
        #pragma unroll
        for (int mi = 0; mi < 2; ++mi)
            #pragma unroll
            for (int nf = 0; nf < 4; ++nf) {
                const int cg = n0 + wn * 32 + nf * 8 + q * 2;
                #pragma unroll
                for (int half = 0; half < 2; ++half) {
                    const int r = m0 + wm * 32 + mi * 16 + arow + half * 8;
                    zf[mi][nf][half] = *(const float2*)(Zt + (size_t)r * HH + cg);
                }
            }

        if (tid == 0) {
            const unsigned tgt = (unsigned)NSTEP_CTAS * (unsigned)t;
            while (*(volatile unsigned*)&g_bar < tgt) __nanosleep(32);
            __threadfence();
        }
        __syncthreads();

        // K-chunk 64 floats (256B rows), stage loader
        auto load_stage = [&](int c, int s) {
            const int kf = c * 64;
            const uint32_t ab = smb + (uint32_t)(s * STG) * 4;
            const uint32_t bb = ab + (uint32_t)SASZ * 4;
            #pragma unroll
            for (int i = 0; i < 4; ++i) {                // A: 64 rows x 256B
                int e = tid + i * 256, r = e >> 4, j = e & 15;
                CPA16(ab + (uint32_t)(r * RS + j * 4) * 4,
                      Asrc + (size_t)(m0 + r) * HH + kf + j * 4);
            }
            #pragma unroll
            for (int i = 0; i < 8; ++i) {                // B: 128 rows x 256B
                int e = tid + i * 256, r = e >> 4, j = e & 15;
                CPA16(bb + (uint32_t)(r * RS + j * 4) * 4,
                      g_Whh + (size_t)(n0 + r) * HH + kf + j * 4);
            }
        };

        #pragma unroll
        for (int c = 0; c < 3; ++c) { load_stage(c, c); CPC(); }

        float acc[2][4][4];
        #pragma unroll
        for (int mi = 0; mi < 2; ++mi)
            #pragma unroll
            for (int nf = 0; nf < 4; ++nf)
                #pragma unroll
                for (int j = 0; j < 4; ++j) acc[mi][nf][j] = 0.f;

        for (int c = 0; c < 16; ++c) {
            CPW2();                       // chunk c landed
            __syncthreads();              // all warps done with slot (c-1)&3
            if (c + 3 < 16) load_stage(c + 3, (c + 3) & 3);   // slot (c-1)&3
            CPC();
            const float* sA = smf + (c & 3) * STG;
            const float* sB = sA + SASZ;
            #pragma unroll
            for (int ks = 0; ks < 8; ++ks) {
                const int col = ks * 8 + q;
                uint32_t a[2][4];
                #pragma unroll
                for (int mi = 0; mi < 2; ++mi) {
                    const float* p = sA + (wm * 32 + mi * 16 + arow) * RS + col;
                    a[mi][0] = __float_as_uint(p[0]);
                    a[mi][1] = __float_as_uint(p[8 * RS]);
                    a[mi][2] = __float_as_uint(p[4]);
                    a[mi][3] = __float_as_uint(p[8 * RS + 4]);
                }
                uint32_t b[4][2];
                #pragma unroll
                for (int nf = 0; nf < 4; ++nf) {
                    const float* p = sB + (wn * 32 + nf * 8 + arow) * RS + col;
                    b[nf][0] = __float_as_uint(p[0]);
                    b[nf][1] = __float_as_uint(p[4]);
                }
                #pragma unroll
                for (int mi = 0; mi < 2; ++mi)
                    #pragma unroll
                    for (int nf = 0; nf < 4; ++nf)
                        MMA_TF32(acc[mi][nf], a[mi], b[nf]);
            }
        }

        // epilogue: tanh(acc + Z_t) -> h[t&1]
        #pragma unroll
        for (int mi = 0; mi < 2; ++mi)
            #pragma unroll
            for (int nf = 0; nf < 4; ++nf) {
                const int cg = n0 + wn * 32 + nf * 8 + q * 2;
                #pragma unroll
                for (int half = 0; half < 2; ++half) {
                    const int r = m0 + wm * 32 + mi * 16 + arow + half * 8;
                    float2 o;
                    o.x = tf32_rn(tanhf(acc[mi][nf][half * 2 + 0] + zf[mi][nf][half].x));
                    o.y = tf32_rn(tanhf(acc[mi][nf][half * 2 + 1] + zf[mi][nf][half].y));
                    *(float2*)(out + (size_t)r * HH + cg) = o;
                }
            }
        __syncthreads();
        if (tid == 0) { __threadfence(); atomicAdd(&g_bar, 1); }
    }
}

// ----------------------------- small kernels --------------------------------
__global__ void conv_av_k(const float4* __restrict__ av, int n8) {
    int i = blockIdx.x * blockDim.x + threadIdx.x;       // 8 floats per thread
    if (i < n8) {
        float4 a = av[2 * i], b = av[2 * i + 1];
        __nv_bfloat162 p0 = __floats2bfloat162_rn(a.x, a.y);
        __nv_bfloat162 p1 = __floats2bfloat162_rn(a.z, a.w);
        __nv_bfloat162 p2 = __floats2bfloat162_rn(b.x, b.y);
        __nv_bfloat162 p3 = __floats2bfloat162_rn(b.z, b.w);
        uint4 o = make_uint4(*(uint32_t*)&p0, *(uint32_t*)&p1,
                             *(uint32_t*)&p2, *(uint32_t*)&p3);
        ((uint4*)g_Xbf)[i] = o;
    }
}

__global__ void conv_W_k(const float4* __restrict__ wih,
                         const float4* __restrict__ whh, int n4) {
    int i = blockIdx.x * blockDim.x + threadIdx.x;
    if (i == 0) g_bar = 0;                                // reset grid barrier
    if (i < n4) {
        float4 a = wih[i];
        __nv_bfloat162 p0 = __floats2bfloat162_rn(a.x, a.y);
        __nv_bfloat162 p1 = __floats2bfloat162_rn(a.z, a.w);
        ((uint2*)g_Wihbf)[i] = make_uint2(*(uint32_t*)&p0, *(uint32_t*)&p1);
        float4 b = whh[i];
        b.x = tf32_rn(b.x); b.y = tf32_rn(b.y); b.z = tf32_rn(b.z); b.w = tf32_rn(b.w);
        ((float4*)g_Whh)[i] = b;
    }
}

__global__ void head_k(const float* __restrict__ Wout,
                       const float* __restrict__ bout) {
    int wid = threadIdx.x >> 5, lane = threadIdx.x & 31;
    int row = blockIdx.x * 8 + wid;
    const float4* hr = (const float4*)(g_h[1] + (size_t)row * HH);
    const float4* wr = (const float4*)Wout;
    float s = 0.f;
    for (int i = lane; i < HH / 4; i += 32) {
        float4 a = hr[i], b = wr[i];
        s += a.x * b.x + a.y * b.y + a.z * b.z + a.w * b.w;
    }
    #pragma unroll
    for (int o = 16; o; o >>= 1) s += __shfl_xor_sync(0xFFFFFFFFu, s, o);
    if (lane == 0) g_p[row] = 1.f / (1.f + expf(-(s + bout[0])));
}

__global__ void loss_k(const float* __restrict__ y, float* __restrict__ out,
                       int out_size) {
    __shared__ float red[32];
    int tid = threadIdx.x;                                // 1024 threads
    float pv = g_p[tid];
    float yb = (y[tid] >= 1e-5f) ? 1.f : 0.f;
    float term = yb * fmaxf(logf(pv), -100.f)
               + (1.f - yb) * fmaxf(log1pf(-pv), -100.f);
    #pragma unroll
    for (int o = 16; o; o >>= 1) term += __shfl_xor_sync(0xFFFFFFFFu, term, o);
    if ((tid & 31) == 0) red[tid >> 5] = term;
    __syncthreads();
    if (tid < 32) {
        float v = red[tid];
        #pragma unroll
        for (int o = 16; o; o >>= 1) v += __shfl_xor_sync(0xFFFFFFFFu, v, o);
        if (tid == 0 && out_size != BB) out[0] = -v / (float)BB;
    }
    if (out_size >= 1 + BB)      out[1 + tid] = pv;
    else if (out_size == BB)     out[tid] = pv;
    for (int i = 1 + BB + tid; i < out_size; i += BB) out[i] = 0.f;
}

// ------------------------------- launcher -----------------------------------
extern "C" void kernel_launch(void* const* d_in, const int* in_sizes, int n_in,
                              void* d_out, int out_size) {
    const float* av   = (const float*)d_in[3];
    const float* y    = (const float*)d_in[4];
    const float* Wih  = (const float*)d_in[5];
    const float* bih  = (const float*)d_in[6];
    const float* Whh  = (const float*)d_in[7];
    const float* bhh  = (const float*)d_in[8];
    const float* Wout = (const float*)d_in[9];
    const float* bout = (const float*)d_in[10];
    (void)in_sizes; (void)n_in;

    constexpr int SMEM_BIG  = 3 * (128 * 36 + 128 * 36) * 4;   // 110592 B
    constexpr int SMEM_STEP = 4 * (64 * 68 + 128 * 68) * 4;    // 208896 B
    cudaFuncSetAttribute(gemm_big,
                         cudaFuncAttributeMaxDynamicSharedMemorySize, SMEM_BIG);
    cudaFuncSetAttribute(steps_k,
                         cudaFuncAttributeMaxDynamicSharedMemorySize, SMEM_STEP);

    // 1) conversions (av -> bf16; W_ih -> bf16; W_hh -> tf32) + barrier reset
    conv_av_k<<<(BB * TT * HH / 8 + 255) / 256, 256>>>((const float4*)av,
                                                       BB * TT * HH / 8);
    conv_W_k<<<(HH * HH / 4 + 255) / 256, 256>>>(
        (const float4*)Wih, (const float4*)Whh, HH * HH / 4);

    // 2) Z = X @ W_ih^T + b_ih + b_hh   (bf16 tensor cores)
    gemm_big<<<dim3(8, 512), 256, SMEM_BIG>>>(bih, bhh);

    // 3) persistent recurrence (tf32), includes h0 = tanh(Z_0)
    steps_k<<<NSTEP_CTAS, 256, SMEM_STEP>>>();

    // 4) head + loss (final h in g_h[1])
    head_k<<<128, 256>>>(Wout, bout);
    loss_k<<<1, BB>>>(y, (float*)d_out, out_size);
}

// round 8
// speedup vs baseline: 1.7879x; 1.4412x over previous
#include <cuda_runtime.h>
#include <cuda_bf16.h>
#include <cstdint>
#include <cstddef>

// ============================================================================
// RNN_4715874091371 — GB300 sm_103a (compute_103 PTX)
//   Z = X @ W_ih^T + (b_ih+b_hh)   bf16 m16n8k16 GEMM (65536x1024x1024)
//   h_t = tanh(Z_t + h_{t-1} @ W_hh^T)  persistent bf16 kernel, 128 CTAs,
//       CTA tile 64x128, warp tile 32x32, K-chunk 64 halves, single-sync
//   p = sigmoid(h @ W_out^T + b_out);  loss = BCE(p, y >= 1e-5)
// Z and tanh stay fp32; h stored bf16 (RN) between steps.
// ============================================================================

static constexpr int TT = 64;
static constexpr int BB = 1024;
static constexpr int HH = 1024;
static constexpr int NSTEP_CTAS = 128;            // 16 m-tiles x 8 n-tiles

// ---------------- device scratch (allocation-free rule) --------------------
__device__ __nv_bfloat16 g_Xbf[(size_t)BB * TT * HH];    // av in bf16 (128MB)
__device__ __nv_bfloat16 g_Wihbf[(size_t)HH * HH];       // W_ih bf16
__device__ __nv_bfloat16 g_Whhbf[(size_t)HH * HH];       // W_hh bf16
__device__ float g_Z[(size_t)TT * BB * HH];               // [t][b][h] fp32
__device__ __nv_bfloat16 g_hbf[2][(size_t)BB * HH];       // ping-pong hidden
__device__ float g_p[BB];
__device__ unsigned g_bar;

#define DEVI __device__ __forceinline__

DEVI uint32_t smem_u32(const void* p) {
    uint32_t a;
    asm("{ .reg .u64 t; cvta.to.shared.u64 t, %1; cvt.u32.u64 %0, t; }"
        : "=r"(a) : "l"(p));
    return a;
}

#define CPA16(dst_b, src) \
    asm volatile("cp.async.cg.shared.global [%0], [%1], 16;" :: "r"(dst_b), "l"(src))
#define CPC()    asm volatile("cp.async.commit_group;" ::: "memory")
#define CPW2()   asm volatile("cp.async.wait_group 2;" ::: "memory")

// bf16 m16n8k16: D += A*B
#define MMA_BF16(d, a, b)                                                       \
    asm("mma.sync.aligned.m16n8k16.row.col.f32.bf16.bf16.f32 "                  \
        "{%0,%1,%2,%3}, {%4,%5,%6,%7}, {%8,%9}, {%0,%1,%2,%3};"                 \
        : "+f"((d)[0]), "+f"((d)[1]), "+f"((d)[2]), "+f"((d)[3])                \
        : "r"((a)[0]), "r"((a)[1]), "r"((a)[2]), "r"((a)[3]),                   \
          "r"((b)[0]), "r"((b)[1]))

// ============================================================================
// Big GEMM (bf16): Z = Xbf @ Wihbf^T + (b_ih+b_hh). Tile 128x128, K-chunk 64
// halves (32 words/row, pad to 36), 16 chunks, 3 stages, 2 CTAs/SM.
// ============================================================================
__global__ __launch_bounds__(256, 2)
void gemm_big(const float* __restrict__ bih, const float* __restrict__ bhh)
{
    constexpr int SASZ = 128 * 36, SBSZ = 128 * 36, STG = SASZ + SBSZ; // words
    extern __shared__ __align__(16) uint32_t sm[];
    const uint32_t smb = smem_u32(sm);

    const int tid  = threadIdx.x;
    const int lane = tid & 31;
    const int wid  = tid >> 5;
    const int wm   = wid >> 2;             // 2 x 4 warp grid; warp tile 64x32
    const int wn   = wid & 3;
    const int n0   = blockIdx.x * 128;
    const int m0   = blockIdx.y * 128;

    auto load_stage = [&](int c, int s) {
        const int kf = c * 64;                               // in halves
        const uint32_t ab = smb + (uint32_t)(s * STG) * 4;
        const uint32_t bb = ab + (uint32_t)SASZ * 4;
        #pragma unroll
        for (int i = 0; i < 4; ++i) {                        // A: 128 x 128B
            int e = tid + i * 256, r = e >> 3, j = e & 7;
            CPA16(ab + (uint32_t)(r * 36 + j * 4) * 4,
                  g_Xbf + (size_t)(m0 + r) * HH + kf + j * 8);
        }
        #pragma unroll
        for (int i = 0; i < 4; ++i) {                        // B: 128 x 128B
            int e = tid + i * 256, r = e >> 3, j = e & 7;
            CPA16(bb + (uint32_t)(r * 36 + j * 4) * 4,
                  g_Wihbf + (size_t)(n0 + r) * HH + kf + j * 8);
        }
    };

    #pragma unroll
    for (int c = 0; c < 3; ++c) { load_stage(c, c); CPC(); }

    float acc[4][4][4];
    #pragma unroll
    for (int mi = 0; mi < 4; ++mi)
        #pragma unroll
        for (int nf = 0; nf < 4; ++nf)
            #pragma unroll
            for (int j = 0; j < 4; ++j) acc[mi][nf][j] = 0.f;

    const int arow  = wm * 64 + (lane >> 2);
    const int q     = lane & 3;

    for (int c = 0; c < 16; ++c) {
        CPW2();
        __syncthreads();
        const uint32_t* sA = sm + (c % 3) * STG;
        const uint32_t* sB = sA + SASZ;
        #pragma unroll
        for (int ks = 0; ks < 4; ++ks) {                     // k16 per MMA
            const int col = ks * 8 + q;                      // word index
            uint32_t a[4][4];
            #pragma unroll
            for (int mi = 0; mi < 4; ++mi) {
                const uint32_t* p = sA + (arow + mi * 16) * 36 + col;
                a[mi][0] = p[0];
                a[mi][1] = p[8 * 36];
                a[mi][2] = p[4];
                a[mi][3] = p[8 * 36 + 4];
            }
            uint32_t b[4][2];
            #pragma unroll
            for (int nf = 0; nf < 4; ++nf) {
                const uint32_t* p = sB + (wn * 32 + nf * 8 + (lane >> 2)) * 36 + col;
                b[nf][0] = p[0];
                b[nf][1] = p[4];
            }
            #pragma unroll
            for (int mi = 0; mi < 4; ++mi)
                #pragma unroll
                for (int nf = 0; nf < 4; ++nf)
                    MMA_BF16(acc[mi][nf], a[mi], b[nf]);
        }
        __syncthreads();
        if (c + 3 < 16) load_stage(c + 3, c % 3);
        CPC();
    }

    // epilogue: + biases, scatter to g_Z[t][b][n]  (m = b*64 + t)
    #pragma unroll
    for (int mi = 0; mi < 4; ++mi) {
        const int r0 = m0 + wm * 64 + mi * 16 + (lane >> 2);
        #pragma unroll
        for (int nf = 0; nf < 4; ++nf) {
            const int cg = n0 + wn * 32 + nf * 8 + q * 2;
            const float bsum0 = bih[cg] + bhh[cg];
            const float bsum1 = bih[cg + 1] + bhh[cg + 1];
            #pragma unroll
            for (int half = 0; half < 2; ++half) {
                const int r = r0 + half * 8;
                float2 o;
                o.x = acc[mi][nf][half * 2 + 0] + bsum0;
                o.y = acc[mi][nf][half * 2 + 1] + bsum1;
                const int b = r >> 6, t = r & 63;
                *(float2*)(g_Z + ((size_t)t * BB + b) * HH + cg) = o;
            }
        }
    }
}

// ============================================================================
// Persistent steps (bf16): 128 CTAs, CTA tile 64x128, warp grid 2x4 (warp
// tile 32x32), K-chunk 64 halves (16 chunks), 4 stages, single sync/chunk.
//   t=0: h0 = tanh(Z_0);  t>=1: h_t = tanh(Z_t + h_{t-1} @ W_hh^T)
// h kept bf16 between steps; Z + tanh in fp32.
// ============================================================================
__global__ __launch_bounds__(256, 1)
void steps_k()
{
    constexpr int MT = 64, NT = 128;
    constexpr int SASZ = MT * 36, SBSZ = NT * 36, STG = SASZ + SBSZ;  // words
    extern __shared__ __align__(16) uint32_t sm[];
    const uint32_t smb = smem_u32(sm);

    const int tid  = threadIdx.x;
    const int lane = tid & 31;
    const int wid  = tid >> 5;
    const int wm   = wid >> 2;             // 2 x 4 warp grid; warp tile 32x32
    const int wn   = wid & 3;
    const int m0   = (blockIdx.x >> 3) * MT;
    const int n0   = (blockIdx.x & 7) * NT;

    // ---- t = 0: h0 = tanh(Z_0) (store bf16) ----
    for (int e = tid; e < MT * NT; e += 256) {
        int r = e >> 7, c = e & 127;
        size_t idx = (size_t)(m0 + r) * HH + n0 + c;
        g_hbf[0][idx] = __float2bfloat16_rn(tanhf(g_Z[idx]));
    }
    __syncthreads();
    if (tid == 0) { __threadfence(); atomicAdd(&g_bar, 1); }

    const int arow = lane >> 2;
    const int q    = lane & 3;

    for (int t = 1; t < TT; ++t) {
        const __nv_bfloat16* __restrict__ Asrc = g_hbf[(t - 1) & 1];
        __nv_bfloat16*       __restrict__ out  = g_hbf[t & 1];
        const float*         __restrict__ Zt   = g_Z + (size_t)t * BB * HH;

        // Z prefetch (independent of h): hide behind barrier wait
        float2 zf[2][4][2];
        #pragma unroll
        for (int mi = 0; mi < 2; ++mi)
            #pragma unroll
            for (int nf = 0; nf < 4; ++nf) {
                const int cg = n0 + wn * 32 + nf * 8 + q * 2;
                #pragma unroll
                for (int half = 0; half < 2; ++half) {
                    const int r = m0 + wm * 32 + mi * 16 + arow + half * 8;
                    zf[mi][nf][half] = *(const float2*)(Zt + (size_t)r * HH + cg);
                }
            }

        if (tid == 0) {
            const unsigned tgt = (unsigned)NSTEP_CTAS * (unsigned)t;
            while (*(volatile unsigned*)&g_bar < tgt) __nanosleep(32);
            __threadfence();
        }
        __syncthreads();

        // K-chunk 64 halves (128B rows), stage loader
        auto load_stage = [&](int c, int s) {
            const int kf = c * 64;                           // in halves
            const uint32_t ab = smb + (uint32_t)(s * STG) * 4;
            const uint32_t bb = ab + (uint32_t)SASZ * 4;
            #pragma unroll
            for (int i = 0; i < 2; ++i) {                    // A: 64 x 128B
                int e = tid + i * 256, r = e >> 3, j = e & 7;
                CPA16(ab + (uint32_t)(r * 36 + j * 4) * 4,
                      Asrc + (size_t)(m0 + r) * HH + kf + j * 8);
            }
            #pragma unroll
            for (int i = 0; i < 4; ++i) {                    // B: 128 x 128B
                int e = tid + i * 256, r = e >> 3, j = e & 7;
                CPA16(bb + (uint32_t)(r * 36 + j * 4) * 4,
                      g_Whhbf + (size_t)(n0 + r) * HH + kf + j * 8);
            }
        };

        #pragma unroll
        for (int c = 0; c < 3; ++c) { load_stage(c, c); CPC(); }

        float acc[2][4][4];
        #pragma unroll
        for (int mi = 0; mi < 2; ++mi)
            #pragma unroll
            for (int nf = 0; nf < 4; ++nf)
                #pragma unroll
                for (int j = 0; j < 4; ++j) acc[mi][nf][j] = 0.f;

        for (int c = 0; c < 16; ++c) {
            CPW2();                       // chunk c landed
            __syncthreads();              // all warps done with slot (c-1)&3
            if (c + 3 < 16) load_stage(c + 3, (c + 3) & 3);
            CPC();
            const uint32_t* sA = sm + (c & 3) * STG;
            const uint32_t* sB = sA + SASZ;
            #pragma unroll
            for (int ks = 0; ks < 4; ++ks) {                 // k16 per MMA
                const int col = ks * 8 + q;
                uint32_t a[2][4];
                #pragma unroll
                for (int mi = 0; mi < 2; ++mi) {
                    const uint32_t* p = sA + (wm * 32 + mi * 16 + arow) * 36 + col;
                    a[mi][0] = p[0];
                    a[mi][1] = p[8 * 36];
                    a[mi][2] = p[4];
                    a[mi][3] = p[8 * 36 + 4];
                }
                uint32_t b[4][2];
                #pragma unroll
                for (int nf = 0; nf < 4; ++nf) {
                    const uint32_t* p = sB + (wn * 32 + nf * 8 + arow) * 36 + col;
                    b[nf][0] = p[0];
                    b[nf][1] = p[4];
                }
                #pragma unroll
                for (int mi = 0; mi < 2; ++mi)
                    #pragma unroll
                    for (int nf = 0; nf < 4; ++nf)
                        MMA_BF16(acc[mi][nf], a[mi], b[nf]);
            }
        }

        // epilogue: tanh(acc + Z_t) -> bf16 h[t&1]
        #pragma unroll
        for (int mi = 0; mi < 2; ++mi)
            #pragma unroll
            for (int nf = 0; nf < 4; ++nf) {
                const int cg = n0 + wn * 32 + nf * 8 + q * 2;
                #pragma unroll
                for (int half = 0; half < 2; ++half) {
                    const int r = m0 + wm * 32 + mi * 16 + arow + half * 8;
                    float ox = tanhf(acc[mi][nf][half * 2 + 0] + zf[mi][nf][half].x);
                    float oy = tanhf(acc[mi][nf][half * 2 + 1] + zf[mi][nf][half].y);
                    __nv_bfloat162 o2 = __floats2bfloat162_rn(ox, oy);
                    *(__nv_bfloat162*)(out + (size_t)r * HH + cg) = o2;
                }
            }
        __syncthreads();
        if (tid == 0) { __threadfence(); atomicAdd(&g_bar, 1); }
    }
}

// ----------------------------- small kernels --------------------------------
__global__ void conv_av_k(const float4* __restrict__ av, int n8) {
    int i = blockIdx.x * blockDim.x + threadIdx.x;       // 8 floats per thread
    if (i < n8) {
        float4 a = av[2 * i], b = av[2 * i + 1];
        __nv_bfloat162 p0 = __floats2bfloat162_rn(a.x, a.y);
        __nv_bfloat162 p1 = __floats2bfloat162_rn(a.z, a.w);
        __nv_bfloat162 p2 = __floats2bfloat162_rn(b.x, b.y);
        __nv_bfloat162 p3 = __floats2bfloat162_rn(b.z, b.w);
        uint4 o = make_uint4(*(uint32_t*)&p0, *(uint32_t*)&p1,
                             *(uint32_t*)&p2, *(uint32_t*)&p3);
        ((uint4*)g_Xbf)[i] = o;
    }
}

__global__ void conv_W_k(const float4* __restrict__ wih,
                         const float4* __restrict__ whh, int n4) {
    int i = blockIdx.x * blockDim.x + threadIdx.x;
    if (i == 0) g_bar = 0;                                // reset grid barrier
    if (i < n4) {
        float4 a = wih[i];
        __nv_bfloat162 p0 = __floats2bfloat162_rn(a.x, a.y);
        __nv_bfloat162 p1 = __floats2bfloat162_rn(a.z, a.w);
        ((uint2*)g_Wihbf)[i] = make_uint2(*(uint32_t*)&p0, *(uint32_t*)&p1);
        float4 b = whh[i];
        __nv_bfloat162 q0 = __floats2bfloat162_rn(b.x, b.y);
        __nv_bfloat162 q1 = __floats2bfloat162_rn(b.z, b.w);
        ((uint2*)g_Whhbf)[i] = make_uint2(*(uint32_t*)&q0, *(uint32_t*)&q1);
    }
}

__global__ void head_k(const float* __restrict__ Wout,
                       const float* __restrict__ bout) {
    int wid = threadIdx.x >> 5, lane = threadIdx.x & 31;
    int row = blockIdx.x * 8 + wid;
    const __nv_bfloat162* hr =
        (const __nv_bfloat162*)(g_hbf[1] + (size_t)row * HH);
    const float2* wr = (const float2*)Wout;
    float s = 0.f;
    for (int i = lane; i < HH / 2; i += 32) {
        float2 hv = __bfloat1622float2(hr[i]);
        float2 wv = wr[i];
        s += hv.x * wv.x + hv.y * wv.y;
    }
    #pragma unroll
    for (int o = 16; o; o >>= 1) s += __shfl_xor_sync(0xFFFFFFFFu, s, o);
    if (lane == 0) g_p[row] = 1.f / (1.f + expf(-(s + bout[0])));
}

__global__ void loss_k(const float* __restrict__ y, float* __restrict__ out,
                       int out_size) {
    __shared__ float red[32];
    int tid = threadIdx.x;                                // 1024 threads
    float pv = g_p[tid];
    float yb = (y[tid] >= 1e-5f) ? 1.f : 0.f;
    float term = yb * fmaxf(logf(pv), -100.f)
               + (1.f - yb) * fmaxf(log1pf(-pv), -100.f);
    #pragma unroll
    for (int o = 16; o; o >>= 1) term += __shfl_xor_sync(0xFFFFFFFFu, term, o);
    if ((tid & 31) == 0) red[tid >> 5] = term;
    __syncthreads();
    if (tid < 32) {
        float v = red[tid];
        #pragma unroll
        for (int o = 16; o; o >>= 1) v += __shfl_xor_sync(0xFFFFFFFFu, v, o);
        if (tid == 0 && out_size != BB) out[0] = -v / (float)BB;
    }
    if (out_size >= 1 + BB)      out[1 + tid] = pv;
    else if (out_size == BB)     out[tid] = pv;
    for (int i = 1 + BB + tid; i < out_size; i += BB) out[i] = 0.f;
}

// ------------------------------- launcher -----------------------------------
extern "C" void kernel_launch(void* const* d_in, const int* in_sizes, int n_in,
                              void* d_out, int out_size) {
    const float* av   = (const float*)d_in[3];
    const float* y    = (const float*)d_in[4];
    const float* Wih  = (const float*)d_in[5];
    const float* bih  = (const float*)d_in[6];
    const float* Whh  = (const float*)d_in[7];
    const float* bhh  = (const float*)d_in[8];
    const float* Wout = (const float*)d_in[9];
    const float* bout = (const float*)d_in[10];
    (void)in_sizes; (void)n_in;

    constexpr int SMEM_BIG  = 3 * (128 * 36 + 128 * 36) * 4;   // 110592 B
    constexpr int SMEM_STEP = 4 * (64 * 36 + 128 * 36) * 4;    // 110592 B
    cudaFuncSetAttribute(gemm_big,
                         cudaFuncAttributeMaxDynamicSharedMemorySize, SMEM_BIG);
    cudaFuncSetAttribute(steps_k,
                         cudaFuncAttributeMaxDynamicSharedMemorySize, SMEM_STEP);

    // 1) conversions (av, W_ih, W_hh -> bf16) + barrier reset
    conv_av_k<<<(BB * TT * HH / 8 + 255) / 256, 256>>>((const float4*)av,
                                                       BB * TT * HH / 8);
    conv_W_k<<<(HH * HH / 4 + 255) / 256, 256>>>(
        (const float4*)Wih, (const float4*)Whh, HH * HH / 4);

    // 2) Z = X @ W_ih^T + b_ih + b_hh   (bf16 tensor cores)
    gemm_big<<<dim3(8, 512), 256, SMEM_BIG>>>(bih, bhh);

    // 3) persistent recurrence (bf16), includes h0 = tanh(Z_0)
    steps_k<<<NSTEP_CTAS, 256, SMEM_STEP>>>();

    // 4) head + loss (final h in g_hbf[1])
    head_k<<<128, 256>>>(Wout, bout);
    loss_k<<<1, BB>>>(y, (float*)d_out, out_size);
}

// round 9
// speedup vs baseline: 1.9907x; 1.1134x over previous
#include <cuda_runtime.h>
#include <cuda_bf16.h>
#include <cstdint>
#include <cstddef>

// ============================================================================
// RNN_4715874091371 — GB300 sm_103a (compute_103 PTX)
//   Z = X @ W_ih^T + (b_ih+b_hh)   bf16 m16n8k16 GEMM, ldmatrix fragments
//   h_t = tanh(Z_t + h_{t-1} @ W_hh^T)  persistent bf16 kernel, 128 CTAs,
//       CTA tile 128x64, W_hh RESIDENT in smem, ldmatrix, per-m-group barriers
//   p = sigmoid(h @ W_out^T + b_out);  loss = BCE(p, y >= 1e-5)
// ============================================================================

static constexpr int TT = 64;
static constexpr int BB = 1024;
static constexpr int HH = 1024;

// ---------------- device scratch (allocation-free rule) --------------------
__device__ __nv_bfloat16 g_Xbf[(size_t)BB * TT * HH];    // av in bf16 (128MB)
__device__ __nv_bfloat16 g_Wihbf[(size_t)HH * HH];       // W_ih bf16
__device__ __nv_bfloat16 g_Whhbf[(size_t)HH * HH];       // W_hh bf16
__device__ float g_Z[(size_t)TT * BB * HH];               // [t][b][h] fp32
__device__ __nv_bfloat16 g_hbf[2][(size_t)BB * HH];       // ping-pong hidden
__device__ float g_p[BB];
__device__ unsigned g_bars[8];                             // per-m-group

#define DEVI __device__ __forceinline__

DEVI uint32_t smem_u32(const void* p) {
    uint32_t a;
    asm("{ .reg .u64 t; cvta.to.shared.u64 t, %1; cvt.u32.u64 %0, t; }"
        : "=r"(a) : "l"(p));
    return a;
}

#define CPA16(dst_b, src) \
    asm volatile("cp.async.cg.shared.global [%0], [%1], 16;" :: "r"(dst_b), "l"(src))
#define CPC()    asm volatile("cp.async.commit_group;" ::: "memory")
#define CPW2()   asm volatile("cp.async.wait_group 2;" ::: "memory")

// bf16 m16n8k16: D += A*B
#define MMA_BF16(d, a, b)                                                       \
    asm("mma.sync.aligned.m16n8k16.row.col.f32.bf16.bf16.f32 "                  \
        "{%0,%1,%2,%3}, {%4,%5,%6,%7}, {%8,%9}, {%0,%1,%2,%3};"                 \
        : "+f"((d)[0]), "+f"((d)[1]), "+f"((d)[2]), "+f"((d)[3])                \
        : "r"((a)[0]), "r"((a)[1]), "r"((a)[2]), "r"((a)[3]),                   \
          "r"((b)[0]), "r"((b)[1]))

// ldmatrix x4: d[0..3] <- four 8x8 b16 matrices, lane groups 0-7/8-15/16-23/24-31
#define LDSM4(d, addr)                                                          \
    asm volatile("ldmatrix.sync.aligned.m8n8.x4.shared.b16 {%0,%1,%2,%3}, [%4];"\
        : "=r"((d)[0]), "=r"((d)[1]), "=r"((d)[2]), "=r"((d)[3]) : "r"(addr))

// ============================================================================
// Big GEMM (bf16): Z = Xbf @ Wihbf^T + (b_ih+b_hh). Tile 128x128, K-chunk 64
// halves (32 words/row, pad 36), 16 chunks, 3 stages, 2 CTAs/SM, ldmatrix.
// ============================================================================
__global__ __launch_bounds__(256, 2)
void gemm_big(const float* __restrict__ bih, const float* __restrict__ bhh)
{
    constexpr int SASZ = 128 * 36, SBSZ = 128 * 36, STG = SASZ + SBSZ; // words
    extern __shared__ __align__(16) uint32_t sm[];
    const uint32_t smb = smem_u32(sm);

    const int tid  = threadIdx.x;
    const int lane = tid & 31;
    const int wid  = tid >> 5;
    const int wm   = wid >> 2;             // 2 x 4 warp grid; warp tile 64x32
    const int wn   = wid & 3;
    const int n0   = blockIdx.x * 128;
    const int m0   = blockIdx.y * 128;

    // ldmatrix per-lane address components
    const int lrA = lane & 15;                       // row 0..15
    const int whA = (lane >> 4) * 4;                 // word offset 0/4
    const int lrB = (lane & 7) | ((lane >> 4) << 3); // row 0..15
    const int wB  = ((lane >> 3) & 1) * 4;           // word offset 0/4

    auto load_stage = [&](int c, int s) {
        const int kf = c * 64;                               // in halves
        const uint32_t ab = smb + (uint32_t)(s * STG) * 4;
        const uint32_t bb = ab + (uint32_t)SASZ * 4;
        #pragma unroll
        for (int i = 0; i < 4; ++i) {                        // A: 128 x 128B
            int e = tid + i * 256, r = e >> 3, j = e & 7;
            CPA16(ab + (uint32_t)(r * 36 + j * 4) * 4,
                  g_Xbf + (size_t)(m0 + r) * HH + kf + j * 8);
        }
        #pragma unroll
        for (int i = 0; i < 4; ++i) {                        // B: 128 x 128B
            int e = tid + i * 256, r = e >> 3, j = e & 7;
            CPA16(bb + (uint32_t)(r * 36 + j * 4) * 4,
                  g_Wihbf + (size_t)(n0 + r) * HH + kf + j * 8);
        }
    };

    #pragma unroll
    for (int c = 0; c < 3; ++c) { load_stage(c, c); CPC(); }

    float acc[4][4][4];
    #pragma unroll
    for (int mi = 0; mi < 4; ++mi)
        #pragma unroll
        for (int nf = 0; nf < 4; ++nf)
            #pragma unroll
            for (int j = 0; j < 4; ++j) acc[mi][nf][j] = 0.f;

    for (int c = 0; c < 16; ++c) {
        CPW2();
        __syncthreads();
        const uint32_t sA = smb + (uint32_t)((c % 3) * STG) * 4;
        const uint32_t sB = sA + (uint32_t)SASZ * 4;
        #pragma unroll
        for (int ks = 0; ks < 4; ++ks) {                     // k16 per MMA
            uint32_t a[4][4];
            #pragma unroll
            for (int mi = 0; mi < 4; ++mi)
                LDSM4(a[mi], sA + (uint32_t)((wm * 64 + mi * 16 + lrA) * 36
                                             + ks * 8 + whA) * 4);
            uint32_t b[4][2];
            #pragma unroll
            for (int nfp = 0; nfp < 2; ++nfp)
                LDSM4((&b[2 * nfp][0]),
                      sB + (uint32_t)((wn * 32 + nfp * 16 + lrB) * 36
                                      + ks * 8 + wB) * 4);
            #pragma unroll
            for (int mi = 0; mi < 4; ++mi)
                #pragma unroll
                for (int nf = 0; nf < 4; ++nf)
                    MMA_BF16(acc[mi][nf], a[mi], b[nf]);
        }
        __syncthreads();
        if (c + 3 < 16) load_stage(c + 3, c % 3);
        CPC();
    }

    // epilogue: + biases, scatter to g_Z[t][b][n]  (m = b*64 + t)
    const int arow = lane >> 2, q = lane & 3;
    #pragma unroll
    for (int mi = 0; mi < 4; ++mi) {
        const int r0 = m0 + wm * 64 + mi * 16 + arow;
        #pragma unroll
        for (int nf = 0; nf < 4; ++nf) {
            const int cg = n0 + wn * 32 + nf * 8 + q * 2;
            const float bsum0 = bih[cg] + bhh[cg];
            const float bsum1 = bih[cg + 1] + bhh[cg + 1];
            #pragma unroll
            for (int half = 0; half < 2; ++half) {
                const int r = r0 + half * 8;
                float2 o;
                o.x = acc[mi][nf][half * 2 + 0] + bsum0;
                o.y = acc[mi][nf][half * 2 + 1] + bsum1;
                const int b = r >> 6, t = r & 63;
                *(float2*)(g_Z + ((size_t)t * BB + b) * HH + cg) = o;
            }
        }
    }
}

// ============================================================================
// Persistent steps (bf16): 128 CTAs (8 m-groups x 16 n-tiles), CTA tile
// 128x64, warp grid 4x2 (warp tile 32x32). W_hh tile RESIDENT in smem
// (64 rows x 1024 halves, stride 516 words). A (=h) K-chunk 64 halves,
// 4 stages, single sync/chunk, ldmatrix fragments, per-m-group barriers.
// ============================================================================
__global__ __launch_bounds__(256, 1)
void steps_k()
{
    constexpr int ASTG = 128 * 36;                 // words per A stage
    constexpr int BOFF = 4 * ASTG;                 // B base (word offset)
    constexpr int RSB  = 516;                      // B row stride (words)
    extern __shared__ __align__(16) uint32_t sm[];
    const uint32_t smb = smem_u32(sm);

    const int tid  = threadIdx.x;
    const int lane = tid & 31;
    const int wid  = tid >> 5;
    const int wm   = wid >> 1;             // 4 x 2 warp grid; warp tile 32x32
    const int wn   = wid & 1;
    const int mg   = blockIdx.x >> 4;      // m-group 0..7
    const int m0   = mg * 128;
    const int n0   = (blockIdx.x & 15) * 64;

    // ---- load resident B = W_hh rows n0..n0+63, full K (group 0) ----
    #pragma unroll
    for (int i = 0; i < 32; ++i) {
        int e = tid + i * 256, r = e >> 7, j = e & 127;
        CPA16(smb + (uint32_t)(BOFF + r * RSB + j * 4) * 4,
              g_Whhbf + (size_t)(n0 + r) * HH + j * 8);
    }
    CPC();

    // ---- t = 0: h0 = tanh(Z_0) on this CTA's tile (128 x 64) ----
    for (int e = tid; e < 128 * 64; e += 256) {
        int r = e >> 6, c = e & 63;
        size_t idx = (size_t)(m0 + r) * HH + n0 + c;
        g_hbf[0][idx] = __float2bfloat16_rn(tanhf(g_Z[idx]));
    }
    __syncthreads();
    if (tid == 0) { __threadfence(); atomicAdd(&g_bars[mg], 1); }

    const int arow = lane >> 2, q = lane & 3;
    const int lrA = lane & 15;
    const int whA = (lane >> 4) * 4;
    const int lrB = (lane & 7) | ((lane >> 4) << 3);
    const int wB  = ((lane >> 3) & 1) * 4;

    for (int t = 1; t < TT; ++t) {
        const __nv_bfloat16* __restrict__ Asrc = g_hbf[(t - 1) & 1];
        __nv_bfloat16*       __restrict__ out  = g_hbf[t & 1];
        const float*         __restrict__ Zt   = g_Z + (size_t)t * BB * HH;

        // Z prefetch (independent of h): hide behind barrier wait
        float2 zf[2][4][2];
        #pragma unroll
        for (int mi = 0; mi < 2; ++mi)
            #pragma unroll
            for (int nf = 0; nf < 4; ++nf) {
                const int cg = n0 + wn * 32 + nf * 8 + q * 2;
                #pragma unroll
                for (int half = 0; half < 2; ++half) {
                    const int r = m0 + wm * 32 + mi * 16 + arow + half * 8;
                    zf[mi][nf][half] = *(const float2*)(Zt + (size_t)r * HH + cg);
                }
            }

        // per-m-group barrier: 16 CTAs of this group wrote h_{t-1}
        if (tid == 0) {
            const unsigned tgt = 16u * (unsigned)t;
            while (*(volatile unsigned*)&g_bars[mg] < tgt) __nanosleep(32);
            __threadfence();
        }
        __syncthreads();

        // A stage loader: chunk c (64 halves) -> slot s
        auto load_stage = [&](int c, int s) {
            const int kf = c * 64;
            const uint32_t ab = smb + (uint32_t)(s * ASTG) * 4;
            #pragma unroll
            for (int i = 0; i < 4; ++i) {                    // A: 128 x 128B
                int e = tid + i * 256, r = e >> 3, j = e & 7;
                CPA16(ab + (uint32_t)(r * 36 + j * 4) * 4,
                      Asrc + (size_t)(m0 + r) * HH + kf + j * 8);
            }
        };

        #pragma unroll
        for (int c = 0; c < 3; ++c) { load_stage(c, c); CPC(); }

        float acc[2][4][4];
        #pragma unroll
        for (int mi = 0; mi < 2; ++mi)
            #pragma unroll
            for (int nf = 0; nf < 4; ++nf)
                #pragma unroll
                for (int j = 0; j < 4; ++j) acc[mi][nf][j] = 0.f;

        for (int c = 0; c < 16; ++c) {
            CPW2();                       // chunk c landed
            __syncthreads();              // all warps done with slot (c-1)&3
            if (c + 3 < 16) load_stage(c + 3, (c + 3) & 3);
            CPC();
            const uint32_t sA = smb + (uint32_t)((c & 3) * ASTG) * 4;
            #pragma unroll
            for (int ks = 0; ks < 4; ++ks) {                 // k16 per MMA
                uint32_t a[2][4];
                #pragma unroll
                for (int mi = 0; mi < 2; ++mi)
                    LDSM4(a[mi], sA + (uint32_t)((wm * 32 + mi * 16 + lrA) * 36
                                                 + ks * 8 + whA) * 4);
                uint32_t b[4][2];
                #pragma unroll
                for (int nfp = 0; nfp < 2; ++nfp)
                    LDSM4((&b[2 * nfp][0]),
                          smb + (uint32_t)(BOFF
                                + (wn * 32 + nfp * 16 + lrB) * RSB
                                + c * 32 + ks * 8 + wB) * 4);
                #pragma unroll
                for (int mi = 0; mi < 2; ++mi)
                    #pragma unroll
                    for (int nf = 0; nf < 4; ++nf)
                        MMA_BF16(acc[mi][nf], a[mi], b[nf]);
            }
        }

        // epilogue: tanh(acc + Z_t) -> bf16 h[t&1]
        #pragma unroll
        for (int mi = 0; mi < 2; ++mi)
            #pragma unroll
            for (int nf = 0; nf < 4; ++nf) {
                const int cg = n0 + wn * 32 + nf * 8 + q * 2;
                #pragma unroll
                for (int half = 0; half < 2; ++half) {
                    const int r = m0 + wm * 32 + mi * 16 + arow + half * 8;
                    float ox = tanhf(acc[mi][nf][half * 2 + 0] + zf[mi][nf][half].x);
                    float oy = tanhf(acc[mi][nf][half * 2 + 1] + zf[mi][nf][half].y);
                    __nv_bfloat162 o2 = __floats2bfloat162_rn(ox, oy);
                    *(__nv_bfloat162*)(out + (size_t)r * HH + cg) = o2;
                }
            }
        __syncthreads();
        if (tid == 0) { __threadfence(); atomicAdd(&g_bars[mg], 1); }
    }
}

// ----------------------------- small kernels --------------------------------
__global__ void conv_av_k(const float4* __restrict__ av, int n8) {
    int i = blockIdx.x * blockDim.x + threadIdx.x;       // 8 floats per thread
    if (i < n8) {
        float4 a = av[2 * i], b = av[2 * i + 1];
        __nv_bfloat162 p0 = __floats2bfloat162_rn(a.x, a.y);
        __nv_bfloat162 p1 = __floats2bfloat162_rn(a.z, a.w);
        __nv_bfloat162 p2 = __floats2bfloat162_rn(b.x, b.y);
        __nv_bfloat162 p3 = __floats2bfloat162_rn(b.z, b.w);
        uint4 o = make_uint4(*(uint32_t*)&p0, *(uint32_t*)&p1,
                             *(uint32_t*)&p2, *(uint32_t*)&p3);
        ((uint4*)g_Xbf)[i] = o;
    }
}

__global__ void conv_W_k(const float4* __restrict__ wih,
                         const float4* __restrict__ whh, int n4) {
    int i = blockIdx.x * blockDim.x + threadIdx.x;
    if (i < 8) g_bars[i] = 0;                             // reset barriers
    if (i < n4) {
        float4 a = wih[i];
        __nv_bfloat162 p0 = __floats2bfloat162_rn(a.x, a.y);
        __nv_bfloat162 p1 = __floats2bfloat162_rn(a.z, a.w);
        ((uint2*)g_Wihbf)[i] = make_uint2(*(uint32_t*)&p0, *(uint32_t*)&p1);
        float4 b = whh[i];
        __nv_bfloat162 q0 = __floats2bfloat162_rn(b.x, b.y);
        __nv_bfloat162 q1 = __floats2bfloat162_rn(b.z, b.w);
        ((uint2*)g_Whhbf)[i] = make_uint2(*(uint32_t*)&q0, *(uint32_t*)&q1);
    }
}

__global__ void head_k(const float* __restrict__ Wout,
                       const float* __restrict__ bout) {
    int wid = threadIdx.x >> 5, lane = threadIdx.x & 31;
    int row = blockIdx.x * 8 + wid;
    const __nv_bfloat162* hr =
        (const __nv_bfloat162*)(g_hbf[1] + (size_t)row * HH);
    const float2* wr = (const float2*)Wout;
    float s = 0.f;
    for (int i = lane; i < HH / 2; i += 32) {
        float2 hv = __bfloat1622float2(hr[i]);
        float2 wv = wr[i];
        s += hv.x * wv.x + hv.y * wv.y;
    }
    #pragma unroll
    for (int o = 16; o; o >>= 1) s += __shfl_xor_sync(0xFFFFFFFFu, s, o);
    if (lane == 0) g_p[row] = 1.f / (1.f + expf(-(s + bout[0])));
}

__global__ void loss_k(const float* __restrict__ y, float* __restrict__ out,
                       int out_size) {
    __shared__ float red[32];
    int tid = threadIdx.x;                                // 1024 threads
    float pv = g_p[tid];
    float yb = (y[tid] >= 1e-5f) ? 1.f : 0.f;
    float term = yb * fmaxf(logf(pv), -100.f)
               + (1.f - yb) * fmaxf(log1pf(-pv), -100.f);
    #pragma unroll
    for (int o = 16; o; o >>= 1) term += __shfl_xor_sync(0xFFFFFFFFu, term, o);
    if ((tid & 31) == 0) red[tid >> 5] = term;
    __syncthreads();
    if (tid < 32) {
        float v = red[tid];
        #pragma unroll
        for (int o = 16; o; o >>= 1) v += __shfl_xor_sync(0xFFFFFFFFu, v, o);
        if (tid == 0 && out_size != BB) out[0] = -v / (float)BB;
    }
    if (out_size >= 1 + BB)      out[1 + tid] = pv;
    else if (out_size == BB)     out[tid] = pv;
    for (int i = 1 + BB + tid; i < out_size; i += BB) out[i] = 0.f;
}

// ------------------------------- launcher -----------------------------------
extern "C" void kernel_launch(void* const* d_in, const int* in_sizes, int n_in,
                              void* d_out, int out_size) {
    const float* av   = (const float*)d_in[3];
    const float* y    = (const float*)d_in[4];
    const float* Wih  = (const float*)d_in[5];
    const float* bih  = (const float*)d_in[6];
    const float* Whh  = (const float*)d_in[7];
    const float* bhh  = (const float*)d_in[8];
    const float* Wout = (const float*)d_in[9];
    const float* bout = (const float*)d_in[10];
    (void)in_sizes; (void)n_in;

    constexpr int SMEM_BIG  = 3 * (128 * 36 + 128 * 36) * 4;     // 110592 B
    constexpr int SMEM_STEP = (4 * 128 * 36 + 64 * 516) * 4;     // 205824 B
    cudaFuncSetAttribute(gemm_big,
                         cudaFuncAttributeMaxDynamicSharedMemorySize, SMEM_BIG);
    cudaFuncSetAttribute(steps_k,
                         cudaFuncAttributeMaxDynamicSharedMemorySize, SMEM_STEP);

    // 1) conversions (av, W_ih, W_hh -> bf16) + barrier reset
    conv_av_k<<<(BB * TT * HH / 8 + 255) / 256, 256>>>((const float4*)av,
                                                       BB * TT * HH / 8);
    conv_W_k<<<(HH * HH / 4 + 255) / 256, 256>>>(
        (const float4*)Wih, (const float4*)Whh, HH * HH / 4);

    // 2) Z = X @ W_ih^T + b_ih + b_hh   (bf16 tensor cores)
    gemm_big<<<dim3(8, 512), 256, SMEM_BIG>>>(bih, bhh);

    // 3) persistent recurrence (bf16), W_hh resident, per-group barriers
    steps_k<<<128, 256, SMEM_STEP>>>();

    // 4) head + loss (final h in g_hbf[1])
    head_k<<<128, 256>>>(Wout, bout);
    loss_k<<<1, BB>>>(y, (float*)d_out, out_size);
}